// round 16
// baseline (speedup 1.0000x reference)
#include <cuda_runtime.h>
#include <cuda_fp16.h>
#include <cstdint>
#include <cstddef>

#define B_    4
#define SEQ   4096
#define NH    16
#define HDIM  32
#define EV    64
#define CD    1024
#define C3    3072
#define LAMB_INIT 0.2f
#define ONE_MINUS_LAMB 0.8f
// q pre-scale: HD^-0.5 * log2(e)  (softmax done in base-2, no max subtraction)
#define QSC ((float)(0.17677669529663687 * 1.4426950408889634))

// Scratch (allocation-free: device globals)
__device__ __half g_qkvh[(size_t)B_ * SEQ * C3];   // [B*N, 3C] f16 (q pre-scaled)
__device__ __half g_xh  [(size_t)B_ * SEQ * CD];   // x in f16
__device__ __half g_wqkv[(size_t)C3 * CD];         // w_qkv f16
__device__ __half g_wprj[(size_t)CD * CD];         // w_proj f16
__device__ __half g_midh[(size_t)B_ * SEQ * CD];   // attention out, f16

// ---------------------------------------------------------------------------
__device__ __forceinline__ uint32_t smem_u32(const void* p) {
    return (uint32_t)__cvta_generic_to_shared(p);
}
__device__ __forceinline__ void ldsm4(uint32_t* r, uint32_t addr) {
    asm volatile("ldmatrix.sync.aligned.m8n8.x4.shared.b16 {%0,%1,%2,%3}, [%4];"
        : "=r"(r[0]), "=r"(r[1]), "=r"(r[2]), "=r"(r[3]) : "r"(addr));
}
__device__ __forceinline__ void ldsm4t(uint32_t* r, uint32_t addr) {
    asm volatile("ldmatrix.sync.aligned.m8n8.x4.trans.shared.b16 {%0,%1,%2,%3}, [%4];"
        : "=r"(r[0]), "=r"(r[1]), "=r"(r[2]), "=r"(r[3]) : "r"(addr));
}
__device__ __forceinline__ void mma_f16(float* d, const uint32_t* a,
                                        uint32_t b0, uint32_t b1) {
    asm volatile("mma.sync.aligned.m16n8k16.row.col.f32.f16.f16.f32 "
        "{%0,%1,%2,%3},{%4,%5,%6,%7},{%8,%9},{%0,%1,%2,%3};"
        : "+f"(d[0]), "+f"(d[1]), "+f"(d[2]), "+f"(d[3])
        : "r"(a[0]), "r"(a[1]), "r"(a[2]), "r"(a[3]), "r"(b0), "r"(b1));
}
__device__ __forceinline__ float ex2(float x) {
    float y; asm("ex2.approx.ftz.f32 %0, %1;" : "=f"(y) : "f"(x));
    return y;
}
__device__ __forceinline__ uint32_t packh2(float a, float b) {
    __half2 h = __floats2half2_rn(a, b);
    return *(uint32_t*)&h;
}
__device__ __forceinline__ void cp16(uint32_t smem_dst, const void* gsrc) {
    asm volatile("cp.async.cg.shared.global [%0], [%1], 16;" :: "r"(smem_dst), "l"(gsrc));
}
#define CP_COMMIT() asm volatile("cp.async.commit_group;")
#define CP_WAIT0()  asm volatile("cp.async.wait_group 0;")

// ---------------------------------------------------------------------------
// fp32 -> f16 convert (n multiple of 8)
// ---------------------------------------------------------------------------
__global__ void conv_f16(const float* __restrict__ s, __half* __restrict__ d, int n)
{
    int i = (blockIdx.x * blockDim.x + threadIdx.x) * 8;
    if (i >= n) return;
    float4 a = *(const float4*)(s + i);
    float4 b = *(const float4*)(s + i + 4);
    __half2 h[4] = { __floats2half2_rn(a.x, a.y), __floats2half2_rn(a.z, a.w),
                     __floats2half2_rn(b.x, b.y), __floats2half2_rn(b.z, b.w) };
    *(uint4*)(d + i) = *(uint4*)h;
}

// ---------------------------------------------------------------------------
// f16 GEMM, DEEP-K variant: block 128x128 x K-chunk 64, 2-stage dynamic smem.
// Halves the sync count vs the 32-K version; 64 HMMA per warp per window.
// 8 warps: wm=(w&1)*64, wn=(w>>1)*32. Same accumulation order over K.
// ---------------------------------------------------------------------------
#define GP2 72   /* padded halves per 64-half row */

template<bool F16OUT>
__global__ __launch_bounds__(256)
void gemm_f16_k64(const __half* __restrict__ A, const __half* __restrict__ Bw,
                  const float* __restrict__ bias, void* __restrict__ Cout,
                  int M, int N, int K)
{
    extern __shared__ __half gsm[];

    const int tid  = threadIdx.x;
    const int w    = tid >> 5, lane = tid & 31;
    const int tg   = lane & 3, gp = lane >> 2;
    const int wm   = (w & 1) << 6;        // 0,64
    const int wn   = (w >> 1) << 5;       // 0,32,64,96
    const int m0   = blockIdx.y << 7, n0 = blockIdx.x << 7;

    const int lrow = tid >> 1;            // 0..127
    const int lc0  = (tid & 1) << 2;      // 0,4 -> 4 chunks of 8 halves each

    const uint32_t matB = 128 * GP2 * 2;  // bytes per matrix per buffer
    const uint32_t bufB = 2 * matB;       // bytes per buffer (A+B)
    const uint32_t As_b = smem_u32(gsm);
    const uint32_t Bs_b = As_b + matB;

    const int a_row = ((lane >> 3) & 1) * 8 + (lane & 7);
    const int a_col = (lane >> 4) * 8;
    const int b_row = (lane >> 4) * 8 + (lane & 7);
    const int b_col = ((lane >> 3) & 1) * 8;

    const __half* Ap = A  + (size_t)(m0 + lrow) * K;
    const __half* Bp = Bw + (size_t)(n0 + lrow) * K;

    // buffer loader: K-chunk starting at k0 -> buffer bsel
    auto load_buf = [&](int k0, int bsel) {
        const uint32_t bo = (uint32_t)bsel * bufB;
        #pragma unroll
        for (int c = 0; c < 4; ++c) {
            const uint32_t off = (uint32_t)((lrow * GP2 + (lc0 + c) * 8) * 2);
            cp16(As_b + bo + off, Ap + k0 + (lc0 + c) * 8);
            cp16(Bs_b + bo + off, Bp + k0 + (lc0 + c) * 8);
        }
        CP_COMMIT();
    };

    load_buf(0, 0);

    float acc[4][4][4] = {};
    const int nT = K >> 6;                // 16 for K=1024

    for (int t = 0; t < nT; ++t) {
        const uint32_t bo = (uint32_t)(t & 1) * bufB;
        CP_WAIT0();
        __syncthreads();
        if (t + 1 < nT) load_buf((t + 1) << 6, (t + 1) & 1);
        #pragma unroll
        for (int ks = 0; ks < 4; ++ks) {
            uint32_t afr[4][4], bfr[2][4];
            #pragma unroll
            for (int mt = 0; mt < 4; ++mt)
                ldsm4(afr[mt], As_b + bo + (uint32_t)(
                    ((wm + mt * 16 + a_row) * GP2 + ks * 16 + a_col) * 2));
            #pragma unroll
            for (int np = 0; np < 2; ++np)
                ldsm4(bfr[np], Bs_b + bo + (uint32_t)(
                    ((wn + np * 16 + b_row) * GP2 + ks * 16 + b_col) * 2));
            #pragma unroll
            for (int mt = 0; mt < 4; ++mt)
                #pragma unroll
                for (int np = 0; np < 2; ++np) {
                    mma_f16(acc[mt][np * 2 + 0], afr[mt], bfr[np][0], bfr[np][1]);
                    mma_f16(acc[mt][np * 2 + 1], afr[mt], bfr[np][2], bfr[np][3]);
                }
        }
    }

    #pragma unroll
    for (int mt = 0; mt < 4; ++mt) {
        #pragma unroll
        for (int nt = 0; nt < 4; ++nt) {
            const int col = n0 + wn + nt * 8 + 2 * tg;
            const int r0  = m0 + wm + mt * 16 + gp;
            if (F16OUT) {
                const float sc = (col < CD) ? QSC : 1.0f;
                __half* Ch = (__half*)Cout;
                *(__half2*)&Ch[(size_t)r0 * N + col] =
                    __floats2half2_rn(acc[mt][nt][0] * sc, acc[mt][nt][1] * sc);
                *(__half2*)&Ch[(size_t)(r0 + 8) * N + col] =
                    __floats2half2_rn(acc[mt][nt][2] * sc, acc[mt][nt][3] * sc);
            } else {
                const float b0 = bias[col], b1 = bias[col + 1];
                float* Cf = (float*)Cout;
                *(float2*)&Cf[(size_t)r0 * N + col] =
                    make_float2(acc[mt][nt][0] + b0, acc[mt][nt][1] + b1);
                *(float2*)&Cf[(size_t)(r0 + 8) * N + col] =
                    make_float2(acc[mt][nt][2] + b0, acc[mt][nt][3] + b1);
            }
        }
    }
}

// ---------------------------------------------------------------------------
// Fused differential attention (R11, byte-identical): branch-split warps,
// 2-buffer, register P, no-max f32 ex2 softmax, deferred l, f16 out.
// ---------------------------------------------------------------------------
#define SQ_P 40
#define SV_P 72

__global__ __launch_bounds__(256, 2)
void diff_attn_f16(const __half* __restrict__ qh,
                   const float* __restrict__ lq1, const float* __restrict__ lk1,
                   const float* __restrict__ lq2, const float* __restrict__ lk2,
                   const float* __restrict__ snw_g,
                   __half* __restrict__ midh)
{
    extern __shared__ __half smh[];
    __half* sq = smh;                 // [2 br][64][40]
    __half* sk = sq + 2 * 64 * SQ_P;  // [2 buf][2 br][64][40]
    __half* sv = sk + 4 * 64 * SQ_P;  // [2 buf][64][72]
    float* s_lam = (float*)(sv + 2 * 64 * SV_P);
    // epilogue exchange regions (alias sk, live only after the main loop)
    float* x_o1 = (float*)sk;                 // 4 warps * 32 lanes * 32 f32 = 16KB
    float* x_l1 = (float*)sk + 4096;          // 4 warps * 16 values

    const int tid  = threadIdx.x;
    const int wid  = tid >> 5, lane = tid & 31;
    const int tg   = lane & 3, gp = lane >> 2;
    const int w4   = wid & 3;                 // warp-in-branch: row group
    const int br   = wid >> 2;                // this warp's branch
    const int r0w  = w4 << 4;                 // first query row
    const int bh   = blockIdx.y;
    const int b    = bh >> 4, h = bh & 15;
    const int n0   = blockIdx.x << 6;

    const __half* base = qh + (size_t)b * SEQ * C3;
    const int hoff = h * EV;

    if (tid == 0) {
        float a = 0.f, c = 0.f;
        #pragma unroll
        for (int d = 0; d < HDIM; ++d) { a += lq1[d] * lk1[d]; c += lq2[d] * lk2[d]; }
        *s_lam = __expf(a) - __expf(c) + LAMB_INIT;
    }

    const uint32_t sq_b = smem_u32(sq);
    const uint32_t sk_b = smem_u32(sk);
    const uint32_t sv_b = smem_u32(sv);

    // ---- prologue loads: Q, K tile0, V tile0 (256 threads, 2 chunks each) ----
    #pragma unroll
    for (int j = 0; j < 2; ++j) {
        const int id = j * 256 + tid;                 // 0..511
        const int lb = id >> 8, row = (id >> 2) & 63, ch = id & 3;
        cp16(sq_b + (uint32_t)(((lb * 64 + row) * SQ_P + ch * 8) * 2),
             base + (size_t)(n0 + row) * C3 + hoff + lb * 32 + ch * 8);
    }
    #pragma unroll
    for (int j = 0; j < 2; ++j) {
        const int id = j * 256 + tid;
        const int lb = id >> 8, row = (id >> 2) & 63, ch = id & 3;
        cp16(sk_b + (uint32_t)(((lb * 64 + row) * SQ_P + ch * 8) * 2),
             base + (size_t)row * C3 + CD + hoff + lb * 32 + ch * 8);
    }
    #pragma unroll
    for (int j = 0; j < 2; ++j) {
        const int id = j * 256 + tid;
        const int row = id >> 3, ch = id & 7;
        cp16(sv_b + (uint32_t)((row * SV_P + ch * 8) * 2),
             base + (size_t)row * C3 + 2 * CD + hoff + ch * 8);
    }
    CP_COMMIT();
    CP_WAIT0();
    __syncthreads();

    // ---- this warp's Q fragments (own branch only) ----
    uint32_t qf[2][4];
    {
        const int qrow = r0w + ((lane >> 3) & 1) * 8 + (lane & 7);
        const int qcol = (lane >> 4) * 8;
        #pragma unroll
        for (int kc = 0; kc < 2; ++kc)
            ldsm4(qf[kc],
                  sq_b + (uint32_t)(((br * 64 + qrow) * SQ_P + kc * 16 + qcol) * 2));
    }

    float o[8][4] = {};
    float lsum[2] = {};               // per-lane partial row sums (rows gp, gp+8)

    const int k_key  = ((lane >> 4)) * 8 + (lane & 7);
    const int k_dblk = ((lane >> 3) & 1) * 8;
    const int v_key  = ((lane >> 3) & 1) * 8 + (lane & 7);
    const int v_e    = (lane >> 4) * 8;

    for (int t = 0; t < SEQ / 64; ++t) {
        const int buf = t & 1;
        if (t + 1 < SEQ / 64) {
            const int nb = buf ^ 1;
            const size_t rbase = (size_t)(t + 1) * 64;
            #pragma unroll
            for (int j = 0; j < 2; ++j) {
                const int id = j * 256 + tid;
                const int lb = id >> 8, row = (id >> 2) & 63, ch = id & 3;
                cp16(sk_b + (uint32_t)((((nb * 2 + lb) * 64 + row) * SQ_P + ch * 8) * 2),
                     base + (rbase + row) * C3 + CD + hoff + lb * 32 + ch * 8);
            }
            #pragma unroll
            for (int j = 0; j < 2; ++j) {
                const int id = j * 256 + tid;
                const int row = id >> 3, ch = id & 7;
                cp16(sv_b + (uint32_t)(((nb * 64 + row) * SV_P + ch * 8) * 2),
                     base + (rbase + row) * C3 + 2 * CD + hoff + ch * 8);
            }
        }
        CP_COMMIT();

        // ---- QK^T + no-max exp; P into registers (FA2 layout) ----
        uint32_t ph[8][2];
        {
            float s[8][4] = {};
            #pragma unroll
            for (int kc = 0; kc < 2; ++kc) {
                uint32_t kf[4][4];
                #pragma unroll
                for (int np = 0; np < 4; ++np)
                    ldsm4(kf[np], sk_b + (uint32_t)(
                        (((buf * 2 + br) * 64 + np * 16 + k_key) * SQ_P
                         + kc * 16 + k_dblk) * 2));
                #pragma unroll
                for (int np = 0; np < 4; ++np) {
                    mma_f16(s[np * 2 + 0], qf[kc], kf[np][0], kf[np][1]);
                    mma_f16(s[np * 2 + 1], qf[kc], kf[np][2], kf[np][3]);
                }
            }
            float ss0 = 0.f, ss1 = 0.f;
            #pragma unroll
            for (int nt = 0; nt < 8; ++nt) {
                const float e00 = ex2(s[nt][0]), e01 = ex2(s[nt][1]);
                const float e10 = ex2(s[nt][2]), e11 = ex2(s[nt][3]);
                ss0 += e00 + e01; ss1 += e10 + e11;
                ph[nt][0] = packh2(e00, e01);
                ph[nt][1] = packh2(e10, e11);
            }
            lsum[0] += ss0;
            lsum[1] += ss1;
        }
        // ---- P @ V (P from registers) ----
        #pragma unroll
        for (int kc = 0; kc < 4; ++kc) {
            uint32_t vf[4][4];
            #pragma unroll
            for (int ep = 0; ep < 4; ++ep)
                ldsm4t(vf[ep], sv_b + (uint32_t)(
                    ((buf * 64 + kc * 16 + v_key) * SV_P + ep * 16 + v_e) * 2));
            uint32_t pa[4] = { ph[2 * kc][0], ph[2 * kc][1],
                               ph[2 * kc + 1][0], ph[2 * kc + 1][1] };
            #pragma unroll
            for (int ep = 0; ep < 4; ++ep) {
                mma_f16(o[ep * 2 + 0], pa, vf[ep][0], vf[ep][1]);
                mma_f16(o[ep * 2 + 1], pa, vf[ep][2], vf[ep][3]);
            }
        }
        CP_WAIT0();
        __syncthreads();
    }

    // ---- reduce l across the 4 lanes of each row group ----
    float lr[2];
    #pragma unroll
    for (int rh = 0; rh < 2; ++rh) {
        float v = lsum[rh];
        v += __shfl_xor_sync(0xffffffffu, v, 1);
        v += __shfl_xor_sync(0xffffffffu, v, 2);
        lr[rh] = v;
    }

    // ---- branch-1 warps export o1, l1 through smem (sk region retired) ----
    if (br == 1) {
        #pragma unroll
        for (int nt = 0; nt < 8; ++nt)
            *(float4*)&x_o1[((w4 * 8 + nt) * 32 + lane) * 4] = *(float4*)o[nt];
        if (tg == 0) {
            x_l1[w4 * 16 + 0 * 8 + gp] = lr[0];
            x_l1[w4 * 16 + 1 * 8 + gp] = lr[1];
        }
    }
    __syncthreads();

    if (br == 0) {
        const float lam = *s_lam;
        float o1[8][4];
        #pragma unroll
        for (int nt = 0; nt < 8; ++nt)
            *(float4*)o1[nt] = *(const float4*)&x_o1[((w4 * 8 + nt) * 32 + lane) * 4];
        const float l1r[2] = { x_l1[w4 * 16 + gp], x_l1[w4 * 16 + 8 + gp] };

        float w0[8], w1[8];
        #pragma unroll
        for (int nt = 0; nt < 8; ++nt) {
            w0[nt] = snw_g[nt * 8 + 2 * tg];
            w1[nt] = snw_g[nt * 8 + 2 * tg + 1];
        }
        #pragma unroll
        for (int rh = 0; rh < 2; ++rh) {
            const float il1 = 1.0f / lr[rh];
            const float il2 = lam / l1r[rh];
            float f[8][2], ss = 0.f;
            #pragma unroll
            for (int nt = 0; nt < 8; ++nt) {
                f[nt][0] = o[nt][2 * rh + 0] * il1 - o1[nt][2 * rh + 0] * il2;
                f[nt][1] = o[nt][2 * rh + 1] * il1 - o1[nt][2 * rh + 1] * il2;
                ss = fmaf(f[nt][0], f[nt][0], fmaf(f[nt][1], f[nt][1], ss));
            }
            ss += __shfl_xor_sync(0xffffffffu, ss, 1);
            ss += __shfl_xor_sync(0xffffffffu, ss, 2);
            const float rn = rsqrtf(ss * (1.0f / EV) + 1e-5f) * ONE_MINUS_LAMB;
            const int n = n0 + r0w + gp + rh * 8;
            __half* op = midh + ((size_t)b * SEQ + n) * CD + h * EV;
            #pragma unroll
            for (int nt = 0; nt < 8; ++nt)
                *(__half2*)&op[nt * 8 + 2 * tg] =
                    __floats2half2_rn(f[nt][0] * rn * w0[nt], f[nt][1] * rn * w1[nt]);
        }
    }
}

// ---------------------------------------------------------------------------
extern "C" void kernel_launch(void* const* d_in, const int* in_sizes, int n_in,
                              void* d_out, int out_size)
{
    const float* x      = (const float*)d_in[0];
    const float* w_qkv  = (const float*)d_in[1];
    const float* w_proj = (const float*)d_in[2];
    const float* b_proj = (const float*)d_in[3];
    const float* lq1    = (const float*)d_in[4];
    const float* lk1    = (const float*)d_in[5];
    const float* lq2    = (const float*)d_in[6];
    const float* lk2    = (const float*)d_in[7];
    const float* snw    = (const float*)d_in[8];
    float* out = (float*)d_out;

    __half *qkvp, *xh, *wq, *wp, *midh;
    cudaGetSymbolAddress((void**)&qkvp, g_qkvh);
    cudaGetSymbolAddress((void**)&xh,   g_xh);
    cudaGetSymbolAddress((void**)&wq,   g_wqkv);
    cudaGetSymbolAddress((void**)&wp,   g_wprj);
    cudaGetSymbolAddress((void**)&midh, g_midh);

    const int smem_attn = (2 * 64 * SQ_P + 4 * 64 * SQ_P + 2 * 64 * SV_P) * 2 + 16;
    cudaFuncSetAttribute(diff_attn_f16,
                         cudaFuncAttributeMaxDynamicSharedMemorySize, smem_attn);
    const int smem_gemm = 2 * 2 * 128 * GP2 * 2;   // 73728 B
    cudaFuncSetAttribute(gemm_f16_k64<true>,
                         cudaFuncAttributeMaxDynamicSharedMemorySize, smem_gemm);
    cudaFuncSetAttribute(gemm_f16_k64<false>,
                         cudaFuncAttributeMaxDynamicSharedMemorySize, smem_gemm);

    const int M = B_ * SEQ;
    const int nx = M * CD, nwq = C3 * CD, nwp = CD * CD;

    conv_f16<<<(nx  / 8 + 255) / 256, 256>>>(x,      xh, nx);
    conv_f16<<<(nwq / 8 + 255) / 256, 256>>>(w_qkv,  wq, nwq);
    conv_f16<<<(nwp / 8 + 255) / 256, 256>>>(w_proj, wp, nwp);

    gemm_f16_k64<true><<<dim3(C3 / 128, M / 128), 256, smem_gemm>>>(
        xh, wq, nullptr, qkvp, M, C3, CD);

    diff_attn_f16<<<dim3(SEQ / 64, B_ * NH), 256, smem_attn>>>(
        qkvp, lq1, lk1, lq2, lk2, snw, midh);

    gemm_f16_k64<false><<<dim3(CD / 128, M / 128), 256, smem_gemm>>>(
        midh, wp, b_proj, out, M, CD, CD);
}

// round 17
// speedup vs baseline: 1.0660x; 1.0660x over previous
#include <cuda_runtime.h>
#include <cuda_fp16.h>
#include <cstdint>
#include <cstddef>

#define B_    4
#define SEQ   4096
#define NH    16
#define HDIM  32
#define EV    64
#define CD    1024
#define C3    3072
#define LAMB_INIT 0.2f
#define ONE_MINUS_LAMB 0.8f
// q pre-scale: HD^-0.5 * log2(e)  (softmax done in base-2, no max subtraction)
#define QSC ((float)(0.17677669529663687 * 1.4426950408889634))

// Scratch (allocation-free: device globals)
__device__ __half g_qkvh[(size_t)B_ * SEQ * C3];   // [B*N, 3C] f16 (q pre-scaled)
__device__ __half g_xh  [(size_t)B_ * SEQ * CD];   // x in f16
__device__ __half g_wqkv[(size_t)C3 * CD];         // w_qkv f16
__device__ __half g_wprj[(size_t)CD * CD];         // w_proj f16
__device__ __half g_midh[(size_t)B_ * SEQ * CD];   // attention out, f16

// ---------------------------------------------------------------------------
__device__ __forceinline__ uint32_t smem_u32(const void* p) {
    return (uint32_t)__cvta_generic_to_shared(p);
}
__device__ __forceinline__ void ldsm4(uint32_t* r, uint32_t addr) {
    asm volatile("ldmatrix.sync.aligned.m8n8.x4.shared.b16 {%0,%1,%2,%3}, [%4];"
        : "=r"(r[0]), "=r"(r[1]), "=r"(r[2]), "=r"(r[3]) : "r"(addr));
}
__device__ __forceinline__ void ldsm4t(uint32_t* r, uint32_t addr) {
    asm volatile("ldmatrix.sync.aligned.m8n8.x4.trans.shared.b16 {%0,%1,%2,%3}, [%4];"
        : "=r"(r[0]), "=r"(r[1]), "=r"(r[2]), "=r"(r[3]) : "r"(addr));
}
__device__ __forceinline__ void mma_f16(float* d, const uint32_t* a,
                                        uint32_t b0, uint32_t b1) {
    asm volatile("mma.sync.aligned.m16n8k16.row.col.f32.f16.f16.f32 "
        "{%0,%1,%2,%3},{%4,%5,%6,%7},{%8,%9},{%0,%1,%2,%3};"
        : "+f"(d[0]), "+f"(d[1]), "+f"(d[2]), "+f"(d[3])
        : "r"(a[0]), "r"(a[1]), "r"(a[2]), "r"(a[3]), "r"(b0), "r"(b1));
}
__device__ __forceinline__ float ex2(float x) {
    float y; asm("ex2.approx.ftz.f32 %0, %1;" : "=f"(y) : "f"(x));
    return y;
}
__device__ __forceinline__ uint32_t packh2(float a, float b) {
    __half2 h = __floats2half2_rn(a, b);
    return *(uint32_t*)&h;
}
__device__ __forceinline__ void cp16(uint32_t smem_dst, const void* gsrc) {
    asm volatile("cp.async.cg.shared.global [%0], [%1], 16;" :: "r"(smem_dst), "l"(gsrc));
}
#define CP_COMMIT() asm volatile("cp.async.commit_group;")
#define CP_WAIT0()  asm volatile("cp.async.wait_group 0;")

// ---------------------------------------------------------------------------
// fused fp32 -> f16 convert for 3 segments (x, w_qkv, w_proj), one launch
// ---------------------------------------------------------------------------
#define NX_   (B_ * SEQ * CD)
#define NWQ_  (C3 * CD)
#define NWP_  (CD * CD)

__global__ void conv_f16_all(const float* __restrict__ sx,  __half* __restrict__ dx,
                             const float* __restrict__ swq, __half* __restrict__ dwq,
                             const float* __restrict__ swp, __half* __restrict__ dwp)
{
    int i = (blockIdx.x * blockDim.x + threadIdx.x) * 8;
    const float* s;
    __half* d;
    if (i < NX_) {
        s = sx; d = dx;
    } else if (i < NX_ + NWQ_) {
        i -= NX_; s = swq; d = dwq;
    } else if (i < NX_ + NWQ_ + NWP_) {
        i -= NX_ + NWQ_; s = swp; d = dwp;
    } else {
        return;
    }
    float4 a = *(const float4*)(s + i);
    float4 b = *(const float4*)(s + i + 4);
    __half2 h[4] = { __floats2half2_rn(a.x, a.y), __floats2half2_rn(a.z, a.w),
                     __floats2half2_rn(b.x, b.y), __floats2half2_rn(b.z, b.w) };
    *(uint4*)(d + i) = *(uint4*)h;
}

// ---------------------------------------------------------------------------
// f16 GEMM (R5/R9/R11-measured variant): block 128x128x32, static smem, 2-stage.
// ---------------------------------------------------------------------------
#define GP 40   /* padded halves per 32-half row */

template<bool F16OUT>
__global__ __launch_bounds__(256, 2)
void gemm_f16_kernel(const __half* __restrict__ A, const __half* __restrict__ Bw,
                     const float* __restrict__ bias, void* __restrict__ Cout,
                     int M, int N, int K)
{
    __shared__ __half As[2][128][GP];
    __shared__ __half Bs[2][128][GP];

    const int tid  = threadIdx.x;
    const int w    = tid >> 5, lane = tid & 31;
    const int tg   = lane & 3, gp = lane >> 2;
    const int wm   = (w & 1) << 6;        // 0,64
    const int wn   = (w >> 1) << 5;       // 0,32,64,96
    const int m0   = blockIdx.y << 7, n0 = blockIdx.x << 7;

    const int lrow = tid >> 1;            // 0..127
    const int lch  = (tid & 1) << 1;      // 0,2

    const uint32_t As_b = smem_u32(&As[0][0][0]);
    const uint32_t Bs_b = smem_u32(&Bs[0][0][0]);
    const uint32_t bufB = 128 * GP * 2;   // bytes per buffer

    const int a_row = ((lane >> 3) & 1) * 8 + (lane & 7);
    const int a_col = (lane >> 4) * 8;
    const int b_row = (lane >> 4) * 8 + (lane & 7);
    const int b_col = ((lane >> 3) & 1) * 8;

    const __half* Ap = A  + (size_t)(m0 + lrow) * K;
    const __half* Bp = Bw + (size_t)(n0 + lrow) * K;

    #pragma unroll
    for (int c = 0; c < 2; ++c) {
        cp16(As_b + (uint32_t)((lrow * GP + (lch + c) * 8) * 2), Ap + (lch + c) * 8);
        cp16(Bs_b + (uint32_t)((lrow * GP + (lch + c) * 8) * 2), Bp + (lch + c) * 8);
    }
    CP_COMMIT();

    float acc[4][4][4] = {};
    const int nT = K >> 5;

    for (int t = 0; t < nT; ++t) {
        const uint32_t bo = (uint32_t)(t & 1) * bufB;
        CP_WAIT0();
        __syncthreads();
        if (t + 1 < nT) {
            const uint32_t nb = (uint32_t)((t + 1) & 1) * bufB;
            const int k0 = (t + 1) << 5;
            #pragma unroll
            for (int c = 0; c < 2; ++c) {
                cp16(As_b + nb + (uint32_t)((lrow * GP + (lch + c) * 8) * 2),
                     Ap + k0 + (lch + c) * 8);
                cp16(Bs_b + nb + (uint32_t)((lrow * GP + (lch + c) * 8) * 2),
                     Bp + k0 + (lch + c) * 8);
            }
        }
        CP_COMMIT();
        #pragma unroll
        for (int ks = 0; ks < 2; ++ks) {
            uint32_t afr[4][4], bfr[2][4];
            #pragma unroll
            for (int mt = 0; mt < 4; ++mt)
                ldsm4(afr[mt], As_b + bo + (uint32_t)(
                    ((wm + mt * 16 + a_row) * GP + ks * 16 + a_col) * 2));
            #pragma unroll
            for (int np = 0; np < 2; ++np)
                ldsm4(bfr[np], Bs_b + bo + (uint32_t)(
                    ((wn + np * 16 + b_row) * GP + ks * 16 + b_col) * 2));
            #pragma unroll
            for (int mt = 0; mt < 4; ++mt)
                #pragma unroll
                for (int np = 0; np < 2; ++np) {
                    mma_f16(acc[mt][np * 2 + 0], afr[mt], bfr[np][0], bfr[np][1]);
                    mma_f16(acc[mt][np * 2 + 1], afr[mt], bfr[np][2], bfr[np][3]);
                }
        }
    }

    #pragma unroll
    for (int mt = 0; mt < 4; ++mt) {
        #pragma unroll
        for (int nt = 0; nt < 4; ++nt) {
            const int col = n0 + wn + nt * 8 + 2 * tg;
            const int r0  = m0 + wm + mt * 16 + gp;
            if (F16OUT) {
                const float sc = (col < CD) ? QSC : 1.0f;
                __half* Ch = (__half*)Cout;
                *(__half2*)&Ch[(size_t)r0 * N + col] =
                    __floats2half2_rn(acc[mt][nt][0] * sc, acc[mt][nt][1] * sc);
                *(__half2*)&Ch[(size_t)(r0 + 8) * N + col] =
                    __floats2half2_rn(acc[mt][nt][2] * sc, acc[mt][nt][3] * sc);
            } else {
                const float b0 = bias[col], b1 = bias[col + 1];
                float* Cf = (float*)Cout;
                *(float2*)&Cf[(size_t)r0 * N + col] =
                    make_float2(acc[mt][nt][0] + b0, acc[mt][nt][1] + b1);
                *(float2*)&Cf[(size_t)(r0 + 8) * N + col] =
                    make_float2(acc[mt][nt][2] + b0, acc[mt][nt][3] + b1);
            }
        }
    }
}

// ---------------------------------------------------------------------------
// Fused differential attention (R11, byte-identical): branch-split warps,
// 2-buffer, register P, no-max f32 ex2 softmax, deferred l, f16 out.
// ---------------------------------------------------------------------------
#define SQ_P 40
#define SV_P 72

__global__ __launch_bounds__(256, 2)
void diff_attn_f16(const __half* __restrict__ qh,
                   const float* __restrict__ lq1, const float* __restrict__ lk1,
                   const float* __restrict__ lq2, const float* __restrict__ lk2,
                   const float* __restrict__ snw_g,
                   __half* __restrict__ midh)
{
    extern __shared__ __half smh[];
    __half* sq = smh;                 // [2 br][64][40]
    __half* sk = sq + 2 * 64 * SQ_P;  // [2 buf][2 br][64][40]
    __half* sv = sk + 4 * 64 * SQ_P;  // [2 buf][64][72]
    float* s_lam = (float*)(sv + 2 * 64 * SV_P);
    // epilogue exchange regions (alias sk, live only after the main loop)
    float* x_o1 = (float*)sk;                 // 4 warps * 32 lanes * 32 f32 = 16KB
    float* x_l1 = (float*)sk + 4096;          // 4 warps * 16 values

    const int tid  = threadIdx.x;
    const int wid  = tid >> 5, lane = tid & 31;
    const int tg   = lane & 3, gp = lane >> 2;
    const int w4   = wid & 3;                 // warp-in-branch: row group
    const int br   = wid >> 2;                // this warp's branch
    const int r0w  = w4 << 4;                 // first query row
    const int bh   = blockIdx.y;
    const int b    = bh >> 4, h = bh & 15;
    const int n0   = blockIdx.x << 6;

    const __half* base = qh + (size_t)b * SEQ * C3;
    const int hoff = h * EV;

    if (tid == 0) {
        float a = 0.f, c = 0.f;
        #pragma unroll
        for (int d = 0; d < HDIM; ++d) { a += lq1[d] * lk1[d]; c += lq2[d] * lk2[d]; }
        *s_lam = __expf(a) - __expf(c) + LAMB_INIT;
    }

    const uint32_t sq_b = smem_u32(sq);
    const uint32_t sk_b = smem_u32(sk);
    const uint32_t sv_b = smem_u32(sv);

    // ---- prologue loads: Q, K tile0, V tile0 (256 threads, 2 chunks each) ----
    #pragma unroll
    for (int j = 0; j < 2; ++j) {
        const int id = j * 256 + tid;                 // 0..511
        const int lb = id >> 8, row = (id >> 2) & 63, ch = id & 3;
        cp16(sq_b + (uint32_t)(((lb * 64 + row) * SQ_P + ch * 8) * 2),
             base + (size_t)(n0 + row) * C3 + hoff + lb * 32 + ch * 8);
    }
    #pragma unroll
    for (int j = 0; j < 2; ++j) {
        const int id = j * 256 + tid;
        const int lb = id >> 8, row = (id >> 2) & 63, ch = id & 3;
        cp16(sk_b + (uint32_t)(((lb * 64 + row) * SQ_P + ch * 8) * 2),
             base + (size_t)row * C3 + CD + hoff + lb * 32 + ch * 8);
    }
    #pragma unroll
    for (int j = 0; j < 2; ++j) {
        const int id = j * 256 + tid;
        const int row = id >> 3, ch = id & 7;
        cp16(sv_b + (uint32_t)((row * SV_P + ch * 8) * 2),
             base + (size_t)row * C3 + 2 * CD + hoff + ch * 8);
    }
    CP_COMMIT();
    CP_WAIT0();
    __syncthreads();

    // ---- this warp's Q fragments (own branch only) ----
    uint32_t qf[2][4];
    {
        const int qrow = r0w + ((lane >> 3) & 1) * 8 + (lane & 7);
        const int qcol = (lane >> 4) * 8;
        #pragma unroll
        for (int kc = 0; kc < 2; ++kc)
            ldsm4(qf[kc],
                  sq_b + (uint32_t)(((br * 64 + qrow) * SQ_P + kc * 16 + qcol) * 2));
    }

    float o[8][4] = {};
    float lsum[2] = {};               // per-lane partial row sums (rows gp, gp+8)

    const int k_key  = ((lane >> 4)) * 8 + (lane & 7);
    const int k_dblk = ((lane >> 3) & 1) * 8;
    const int v_key  = ((lane >> 3) & 1) * 8 + (lane & 7);
    const int v_e    = (lane >> 4) * 8;

    for (int t = 0; t < SEQ / 64; ++t) {
        const int buf = t & 1;
        if (t + 1 < SEQ / 64) {
            const int nb = buf ^ 1;
            const size_t rbase = (size_t)(t + 1) * 64;
            #pragma unroll
            for (int j = 0; j < 2; ++j) {
                const int id = j * 256 + tid;
                const int lb = id >> 8, row = (id >> 2) & 63, ch = id & 3;
                cp16(sk_b + (uint32_t)((((nb * 2 + lb) * 64 + row) * SQ_P + ch * 8) * 2),
                     base + (rbase + row) * C3 + CD + hoff + lb * 32 + ch * 8);
            }
            #pragma unroll
            for (int j = 0; j < 2; ++j) {
                const int id = j * 256 + tid;
                const int row = id >> 3, ch = id & 7;
                cp16(sv_b + (uint32_t)(((nb * 64 + row) * SV_P + ch * 8) * 2),
                     base + (rbase + row) * C3 + 2 * CD + hoff + ch * 8);
            }
        }
        CP_COMMIT();

        // ---- QK^T + no-max exp; P into registers (FA2 layout) ----
        uint32_t ph[8][2];
        {
            float s[8][4] = {};
            #pragma unroll
            for (int kc = 0; kc < 2; ++kc) {
                uint32_t kf[4][4];
                #pragma unroll
                for (int np = 0; np < 4; ++np)
                    ldsm4(kf[np], sk_b + (uint32_t)(
                        (((buf * 2 + br) * 64 + np * 16 + k_key) * SQ_P
                         + kc * 16 + k_dblk) * 2));
                #pragma unroll
                for (int np = 0; np < 4; ++np) {
                    mma_f16(s[np * 2 + 0], qf[kc], kf[np][0], kf[np][1]);
                    mma_f16(s[np * 2 + 1], qf[kc], kf[np][2], kf[np][3]);
                }
            }
            float ss0 = 0.f, ss1 = 0.f;
            #pragma unroll
            for (int nt = 0; nt < 8; ++nt) {
                const float e00 = ex2(s[nt][0]), e01 = ex2(s[nt][1]);
                const float e10 = ex2(s[nt][2]), e11 = ex2(s[nt][3]);
                ss0 += e00 + e01; ss1 += e10 + e11;
                ph[nt][0] = packh2(e00, e01);
                ph[nt][1] = packh2(e10, e11);
            }
            lsum[0] += ss0;
            lsum[1] += ss1;
        }
        // ---- P @ V (P from registers) ----
        #pragma unroll
        for (int kc = 0; kc < 4; ++kc) {
            uint32_t vf[4][4];
            #pragma unroll
            for (int ep = 0; ep < 4; ++ep)
                ldsm4t(vf[ep], sv_b + (uint32_t)(
                    ((buf * 64 + kc * 16 + v_key) * SV_P + ep * 16 + v_e) * 2));
            uint32_t pa[4] = { ph[2 * kc][0], ph[2 * kc][1],
                               ph[2 * kc + 1][0], ph[2 * kc + 1][1] };
            #pragma unroll
            for (int ep = 0; ep < 4; ++ep) {
                mma_f16(o[ep * 2 + 0], pa, vf[ep][0], vf[ep][1]);
                mma_f16(o[ep * 2 + 1], pa, vf[ep][2], vf[ep][3]);
            }
        }
        CP_WAIT0();
        __syncthreads();
    }

    // ---- reduce l across the 4 lanes of each row group ----
    float lr[2];
    #pragma unroll
    for (int rh = 0; rh < 2; ++rh) {
        float v = lsum[rh];
        v += __shfl_xor_sync(0xffffffffu, v, 1);
        v += __shfl_xor_sync(0xffffffffu, v, 2);
        lr[rh] = v;
    }

    // ---- branch-1 warps export o1, l1 through smem (sk region retired) ----
    if (br == 1) {
        #pragma unroll
        for (int nt = 0; nt < 8; ++nt)
            *(float4*)&x_o1[((w4 * 8 + nt) * 32 + lane) * 4] = *(float4*)o[nt];
        if (tg == 0) {
            x_l1[w4 * 16 + 0 * 8 + gp] = lr[0];
            x_l1[w4 * 16 + 1 * 8 + gp] = lr[1];
        }
    }
    __syncthreads();

    if (br == 0) {
        const float lam = *s_lam;
        float o1[8][4];
        #pragma unroll
        for (int nt = 0; nt < 8; ++nt)
            *(float4*)o1[nt] = *(const float4*)&x_o1[((w4 * 8 + nt) * 32 + lane) * 4];
        const float l1r[2] = { x_l1[w4 * 16 + gp], x_l1[w4 * 16 + 8 + gp] };

        float w0[8], w1[8];
        #pragma unroll
        for (int nt = 0; nt < 8; ++nt) {
            w0[nt] = snw_g[nt * 8 + 2 * tg];
            w1[nt] = snw_g[nt * 8 + 2 * tg + 1];
        }
        #pragma unroll
        for (int rh = 0; rh < 2; ++rh) {
            const float il1 = 1.0f / lr[rh];
            const float il2 = lam / l1r[rh];
            float f[8][2], ss = 0.f;
            #pragma unroll
            for (int nt = 0; nt < 8; ++nt) {
                f[nt][0] = o[nt][2 * rh + 0] * il1 - o1[nt][2 * rh + 0] * il2;
                f[nt][1] = o[nt][2 * rh + 1] * il1 - o1[nt][2 * rh + 1] * il2;
                ss = fmaf(f[nt][0], f[nt][0], fmaf(f[nt][1], f[nt][1], ss));
            }
            ss += __shfl_xor_sync(0xffffffffu, ss, 1);
            ss += __shfl_xor_sync(0xffffffffu, ss, 2);
            const float rn = rsqrtf(ss * (1.0f / EV) + 1e-5f) * ONE_MINUS_LAMB;
            const int n = n0 + r0w + gp + rh * 8;
            __half* op = midh + ((size_t)b * SEQ + n) * CD + h * EV;
            #pragma unroll
            for (int nt = 0; nt < 8; ++nt)
                *(__half2*)&op[nt * 8 + 2 * tg] =
                    __floats2half2_rn(f[nt][0] * rn * w0[nt], f[nt][1] * rn * w1[nt]);
        }
    }
}

// ---------------------------------------------------------------------------
extern "C" void kernel_launch(void* const* d_in, const int* in_sizes, int n_in,
                              void* d_out, int out_size)
{
    const float* x      = (const float*)d_in[0];
    const float* w_qkv  = (const float*)d_in[1];
    const float* w_proj = (const float*)d_in[2];
    const float* b_proj = (const float*)d_in[3];
    const float* lq1    = (const float*)d_in[4];
    const float* lk1    = (const float*)d_in[5];
    const float* lq2    = (const float*)d_in[6];
    const float* lk2    = (const float*)d_in[7];
    const float* snw    = (const float*)d_in[8];
    float* out = (float*)d_out;

    __half *qkvp, *xh, *wq, *wp, *midh;
    cudaGetSymbolAddress((void**)&qkvp, g_qkvh);
    cudaGetSymbolAddress((void**)&xh,   g_xh);
    cudaGetSymbolAddress((void**)&wq,   g_wqkv);
    cudaGetSymbolAddress((void**)&wp,   g_wprj);
    cudaGetSymbolAddress((void**)&midh, g_midh);

    const int smem_attn = (2 * 64 * SQ_P + 4 * 64 * SQ_P + 2 * 64 * SV_P) * 2 + 16;
    cudaFuncSetAttribute(diff_attn_f16,
                         cudaFuncAttributeMaxDynamicSharedMemorySize, smem_attn);

    const int M = B_ * SEQ;
    const int ntot = NX_ + NWQ_ + NWP_;

    conv_f16_all<<<(ntot / 8 + 255) / 256, 256>>>(x, xh, w_qkv, wq, w_proj, wp);

    gemm_f16_kernel<true><<<dim3(C3 / 128, M / 128), 256>>>(
        xh, wq, nullptr, qkvp, M, C3, CD);

    diff_attn_f16<<<dim3(SEQ / 64, B_ * NH), 256, smem_attn>>>(
        qkvp, lq1, lk1, lq2, lk2, snw, midh);

    gemm_f16_kernel<false><<<dim3(CD / 128, M / 128), 256>>>(
        midh, wp, b_proj, out, M, CD, CD);
}